// round 6
// baseline (speedup 1.0000x reference)
#include <cuda_runtime.h>

#define Bn 8
#define Cn 64
#define Hn 128
#define Wn 128
#define On 64
#define KKn 9
#define HWn (Hn*Wn)

// Scratch: NHWC-transposed data and [k][c][o]-transposed weight.
__device__ float g_dT[Bn*HWn*Cn];     // 33.5 MB
__device__ float g_Wt[KKn*Cn*On];     // 147 KB

// ---------------- data transpose: NCHW -> NHWC ----------------
__global__ void transpose_data_k(const float* __restrict__ data) {
    __shared__ float tile[32][33];
    int b  = blockIdx.z;
    int c0 = blockIdx.y * 32;
    int p0 = blockIdx.x * 32;
    int tx = threadIdx.x, ty = threadIdx.y;
#pragma unroll
    for (int i = 0; i < 4; i++) {
        int c = c0 + ty + i * 8;
        tile[ty + i * 8][tx] = data[(b * Cn + c) * HWn + p0 + tx];
    }
    __syncthreads();
#pragma unroll
    for (int i = 0; i < 4; i++) {
        int p = p0 + ty + i * 8;
        g_dT[(b * HWn + p) * Cn + c0 + tx] = tile[tx][ty + i * 8];
    }
}

// ---------------- weight transpose: [o][c][k] -> [k][c][o] ----------------
__global__ void transpose_w_k(const float* __restrict__ w) {
    int i = blockIdx.x * 256 + threadIdx.x;
    if (i < On * Cn * KKn) {
        int k = i % KKn;
        int c = (i / KKn) % Cn;
        int o = i / (KKn * Cn);
        g_Wt[(k * Cn + c) * On + o] = w[i];
    }
}

// ---------------- main kernel ----------------
// Block: (b, 2 output rows) = 256 pixels. 256 threads.
// smem: sW[64c][64o] (16KB) + sS[64c][256pix swizzled] (64KB)
//       + per-pixel corner weights (4KB) + corner offsets (4KB) = 90112 B.
#define FMA4(acc, s, f) do { (acc).x += (f)*(s).x; (acc).y += (f)*(s).y; \
                             (acc).z += (f)*(s).z; (acc).w += (f)*(s).w; } while(0)

__global__ void __launch_bounds__(256, 2)
deform_main_k(const float* __restrict__ offset, float* __restrict__ out) {
    extern __shared__ float smem[];
    float* sW  = smem;                   // 4096 floats
    float* sS  = smem + 4096;            // 16384 floats
    float* sWt = smem + 4096 + 16384;    // 1024 floats (float4/pixel)
    int*   sOf = (int*)(smem + 4096 + 16384 + 1024); // 1024 ints (int4/pixel)

    int b  = blockIdx.y;
    int h0 = blockIdx.x * 2;
    int tid = threadIdx.x;
    int tx = tid & 31, ty = tid >> 5;

    const float* dB = g_dT + (size_t)b * HWn * Cn;

    float4 accA[8], accB[8];
#pragma unroll
    for (int i = 0; i < 8; i++) {
        accA[i] = make_float4(0.f, 0.f, 0.f, 0.f);
        accB[i] = make_float4(0.f, 0.f, 0.f, 0.f);
    }

#pragma unroll 1
    for (int kk = 0; kk < KKn; kk++) {
        __syncthreads();  // protect smem from previous iteration's readers

        // ---- per-pixel sampling params (one pixel per thread) ----
        {
            int p  = tid;
            int hh = h0 + (p >> 7);
            int ww = p & 127;
            const float* ob = offset + (((size_t)b * 18 + 2 * kk) * Hn + hh) * Wn + ww;
            float oy = ob[0];
            float ox = ob[HWn];
            int ki = kk / 3, kj = kk - ki * 3;
            float py = oy + (float)(hh - 1 + ki);
            float px = ox + (float)(ww - 1 + kj);
            float fy = floorf(py), fx = floorf(px);
            float ly = py - fy,  lx = px - fx;
            int y0 = (int)fy, x0 = (int)fx;
            int y1 = y0 + 1, x1 = x0 + 1;
            float vy0 = (y0 >= 0 && y0 < Hn) ? 1.f : 0.f;
            float vy1 = (y1 >= 0 && y1 < Hn) ? 1.f : 0.f;
            float vx0 = (x0 >= 0 && x0 < Wn) ? 1.f : 0.f;
            float vx1 = (x1 >= 0 && x1 < Wn) ? 1.f : 0.f;
            int cy0 = max(0, min(Hn - 1, y0)), cy1 = max(0, min(Hn - 1, y1));
            int cx0 = max(0, min(Wn - 1, x0)), cx1 = max(0, min(Wn - 1, x1));
            float w00 = (1.f - ly) * (1.f - lx) * vy0 * vx0;
            float w01 = (1.f - ly) * lx         * vy0 * vx1;
            float w10 = ly         * (1.f - lx) * vy1 * vx0;
            float w11 = ly         * lx         * vy1 * vx1;
            ((int4*)sOf)[p] = make_int4((cy0 * Wn + cx0) * Cn, (cy0 * Wn + cx1) * Cn,
                                        (cy1 * Wn + cx0) * Cn, (cy1 * Wn + cx1) * Cn);
            ((float4*)sWt)[p] = make_float4(w00, w01, w10, w11);
        }

        // ---- stage weight tile for this k: [c][o], coalesced ----
        {
            const float4* src = (const float4*)(g_Wt + kk * Cn * On);
            float4* dst = (float4*)sW;
#pragma unroll
            for (int r = 0; r < 4; r++) dst[tid + 256 * r] = src[tid + 256 * r];
        }
        __syncthreads();

        // ---- sampling: NHWC float4 gathers, swizzled STS into sS[c][pix] ----
        {
            int cg = tid & 15;       // channel group: c = 4*cg .. 4*cg+3
            int pl = tid >> 4;       // pixel lane
            const float* dC = dB + cg * 4;
#pragma unroll
            for (int it = 0; it < 16; it++) {
                int p = pl + it * 16;
                int4   a  = ((int4*)sOf)[p];
                float4 wv = ((float4*)sWt)[p];
                float4 v00 = *(const float4*)(dC + a.x);
                float4 v01 = *(const float4*)(dC + a.y);
                float4 v10 = *(const float4*)(dC + a.z);
                float4 v11 = *(const float4*)(dC + a.w);
                float4 s;
                s.x = wv.x * v00.x + wv.y * v01.x + wv.z * v10.x + wv.w * v11.x;
                s.y = wv.x * v00.y + wv.y * v01.y + wv.z * v10.y + wv.w * v11.y;
                s.z = wv.x * v00.z + wv.y * v01.z + wv.z * v10.z + wv.w * v11.z;
                s.w = wv.x * v00.w + wv.y * v01.w + wv.z * v10.w + wv.w * v11.w;
                // XOR swizzle on 16B groups: col4 = (pix>>2) ^ ((c>>2)&7); (c>>2)&7 == cg&7
                int col = 4 * ((p >> 2) ^ (cg & 7)) + (p & 3);
                float* ss = sS + (cg * 4) * 256 + col;
                ss[0]   = s.x;
                ss[256] = s.y;
                ss[512] = s.z;
                ss[768] = s.w;
            }
        }
        __syncthreads();

        // ---- GEMM: acc[o=8][pix=8] += W[c][o] * S[c][pix] ----
        {
            const float4* sS4 = (const float4*)sS;
            const float4* sW4 = (const float4*)sW;
#pragma unroll 2
            for (int c = 0; c < 64; c++) {
                int sw = (c >> 2) & 7;
                float4 a  = sS4[c * 64 + (tx ^ sw)];        // pixels 4tx..4tx+3   (row h0)
                float4 bb = sS4[c * 64 + 32 + (tx ^ sw)];   // pixels 128+4tx..+3  (row h0+1)
                float4 w0 = sW4[c * 16 + ty * 2];           // o = 8ty..8ty+3 (broadcast)
                float4 w1 = sW4[c * 16 + ty * 2 + 1];       // o = 8ty+4..8ty+7
                FMA4(accA[0], a, w0.x); FMA4(accB[0], bb, w0.x);
                FMA4(accA[1], a, w0.y); FMA4(accB[1], bb, w0.y);
                FMA4(accA[2], a, w0.z); FMA4(accB[2], bb, w0.z);
                FMA4(accA[3], a, w0.w); FMA4(accB[3], bb, w0.w);
                FMA4(accA[4], a, w1.x); FMA4(accB[4], bb, w1.x);
                FMA4(accA[5], a, w1.y); FMA4(accB[5], bb, w1.y);
                FMA4(accA[6], a, w1.z); FMA4(accB[6], bb, w1.z);
                FMA4(accA[7], a, w1.w); FMA4(accB[7], bb, w1.w);
            }
        }
    }

    // ---- epilogue: out[b][o][h][w], coalesced float4 stores ----
#pragma unroll
    for (int i = 0; i < 8; i++) {
        int o = ty * 8 + i;
        float* op = out + (((size_t)b * On + o) * Hn + h0) * Wn;
        ((float4*)op)[tx]        = accA[i];  // row h0
        ((float4*)(op + Wn))[tx] = accB[i];  // row h0+1
    }
}

extern "C" void kernel_launch(void* const* d_in, const int* in_sizes, int n_in,
                              void* d_out, int out_size) {
    const float* data   = (const float*)d_in[0];
    const float* offset = (const float*)d_in[1];
    const float* weight = (const float*)d_in[2];
    float* out = (float*)d_out;

    transpose_data_k<<<dim3(HWn / 32, Cn / 32, Bn), dim3(32, 8)>>>(data);
    transpose_w_k<<<(KKn * Cn * On + 255) / 256, 256>>>(weight);

    cudaFuncSetAttribute(deform_main_k,
                         cudaFuncAttributeMaxDynamicSharedMemorySize, 90112);
    deform_main_k<<<dim3(Hn / 2, Bn), 256, 90112>>>(offset, out);
}